// round 10
// baseline (speedup 1.0000x reference)
#include <cuda_runtime.h>
#include <cstdint>

#define T_STEPS 8192
#define H_DIM 256
#define E_DIM 256
#define G_DIM 1024   // 4*H
#define CL 8         // cluster size

// 32 MB scratch for xg = emb@W_ih^T + bias  (allocation-free rule: device global)
__device__ float g_xg[(size_t)T_STEPS * G_DIM];

// ---------------------------------------------------------------------------
// helpers
// ---------------------------------------------------------------------------
__device__ __forceinline__ uint32_t smem_u32(const void* p) {
    uint32_t a;
    asm("{ .reg .u64 t; cvta.to.shared.u64 t, %1; cvt.u32.u64 %0, t; }"
        : "=r"(a) : "l"(p));
    return a;
}

__device__ __forceinline__ void ffma2(unsigned long long& d,
                                      unsigned long long a,
                                      unsigned long long b) {
    asm("fma.rn.f32x2 %0, %1, %2, %0;" : "+l"(d) : "l"(a), "l"(b));
}

__device__ __forceinline__ float lo32(unsigned long long v) {
    return __uint_as_float((uint32_t)v);
}
__device__ __forceinline__ float hi32(unsigned long long v) {
    return __uint_as_float((uint32_t)(v >> 32));
}

__device__ __forceinline__ float tanh_fast(float x) {
    float r;
    asm("tanh.approx.f32 %0, %1;" : "=f"(r) : "f"(x));
    return r;
}
// sigmoid(x) = 0.5*tanh(0.5x) + 0.5   (MUFU tanh, no div)
__device__ __forceinline__ float sigmoid_fast(float x) {
    return fmaf(0.5f, tanh_fast(0.5f * x), 0.5f);
}

__device__ __forceinline__ void mbar_wait(uint32_t addr, uint32_t parity) {
    uint32_t done;
    asm volatile(
        "{\n\t.reg .pred p;\n\t"
        "mbarrier.try_wait.parity.acquire.cta.shared::cta.b64 p, [%1], %2;\n\t"
        "selp.b32 %0, 1, 0, p;\n\t}"
        : "=r"(done) : "r"(addr), "r"(parity) : "memory");
    if (!done) {
        asm volatile(
            "{\n\t.reg .pred P1;\n"
            "WL_%=:\n\t"
            "mbarrier.try_wait.parity.acquire.cta.shared::cta.b64 P1, [%0], %1, 0x989680;\n\t"
            "@P1 bra.uni WD_%=;\n\t"
            "bra.uni WL_%=;\n"
            "WD_%=:\n\t}"
            :: "r"(addr), "r"(parity) : "memory");
    }
}

// ---------------------------------------------------------------------------
// Kernel A: xg[t][r] = sum_k emb[tokens[t]][k] * W_ih[r][k] + (b_ih[r]+b_hh[r])
// ---------------------------------------------------------------------------
__global__ __launch_bounds__(256) void xg_gemm(const int* __restrict__ tokens,
                                               const float* __restrict__ emb,
                                               const float* __restrict__ Wih,
                                               const float* __restrict__ bih,
                                               const float* __restrict__ bhh) {
    __shared__ __align__(16) float As[32][132];
    __shared__ __align__(16) float Bs[32][132];
    __shared__ int stok[128];

    const int tid = threadIdx.x;
    const int t0 = blockIdx.y * 128;
    const int r0 = blockIdx.x * 128;

    if (tid < 128) stok[tid] = tokens[t0 + tid];
    __syncthreads();

    const int ty = tid >> 4;
    const int tx = tid & 15;

    float acc[8][8];
#pragma unroll
    for (int i = 0; i < 8; i++)
#pragma unroll
        for (int j = 0; j < 8; j++) acc[i][j] = 0.0f;

    for (int k0 = 0; k0 < E_DIM; k0 += 32) {
#pragma unroll
        for (int q = 0; q < 4; q++) {
            int v = q * 256 + tid;
            int row = v >> 3;
            int c4 = v & 7;
            float4 a = *(const float4*)(emb + (size_t)stok[row] * E_DIM + k0 + c4 * 4);
            As[c4 * 4 + 0][row] = a.x; As[c4 * 4 + 1][row] = a.y;
            As[c4 * 4 + 2][row] = a.z; As[c4 * 4 + 3][row] = a.w;
            float4 b = *(const float4*)(Wih + (size_t)(r0 + row) * E_DIM + k0 + c4 * 4);
            Bs[c4 * 4 + 0][row] = b.x; Bs[c4 * 4 + 1][row] = b.y;
            Bs[c4 * 4 + 2][row] = b.z; Bs[c4 * 4 + 3][row] = b.w;
        }
        __syncthreads();

#pragma unroll
        for (int k = 0; k < 32; k++) {
            float a[8], b[8];
            float4 a0 = *(const float4*)&As[k][ty * 8];
            float4 a1 = *(const float4*)&As[k][ty * 8 + 4];
            float4 b0 = *(const float4*)&Bs[k][tx * 8];
            float4 b1 = *(const float4*)&Bs[k][tx * 8 + 4];
            a[0]=a0.x; a[1]=a0.y; a[2]=a0.z; a[3]=a0.w;
            a[4]=a1.x; a[5]=a1.y; a[6]=a1.z; a[7]=a1.w;
            b[0]=b0.x; b[1]=b0.y; b[2]=b0.z; b[3]=b0.w;
            b[4]=b1.x; b[5]=b1.y; b[6]=b1.z; b[7]=b1.w;
#pragma unroll
            for (int i = 0; i < 8; i++)
#pragma unroll
                for (int j = 0; j < 8; j++)
                    acc[i][j] = fmaf(a[i], b[j], acc[i][j]);
        }
        __syncthreads();
    }

#pragma unroll
    for (int j = 0; j < 8; j++) {
        int r = r0 + tx * 8 + j;
        float bias = bih[r] + bhh[r];
#pragma unroll
        for (int i = 0; i < 8; i++) {
            g_xg[(size_t)(t0 + ty * 8 + i) * G_DIM + r] = acc[i][j] + bias;
        }
    }
}

// ---------------------------------------------------------------------------
// Kernel B: persistent 8-CTA cluster LSTM scan — single-phase + st.async.
//   Warp w owns elems 4w..4w+3 (global E = 32*rank + 4w + (l&3)).
//   Lane l: eidx = l&3, K-slice s = l>>2 (8 slices x 32 floats).
//   Each warp: wait combined barrier -> LDS h -> 64 f32x2 FMA -> shuffle
//   reduce (xor 4,8,16) -> lanes 0-3 activations (tanh.approx; c in-lane)
//   -> pack pairs -> lanes 0-15 st.async b64 packets straight to all 8
//   CTAs' hbuf[(t+1)&1] (lane l: packet l>>3, dest l&7). No __syncthreads,
//   no phase 2, no staging.
//
//   Barriers: bar2[parity], count=1, expect_tx=1024B (8 src x 8 warps x
//   2 pkts x 8B). Pre-loop arms bar1 for t=1. Step t: wait bar[t&1] at
//   parity ((t-1)>>1)&1, then tid0 re-arms it for t+2 BEFORE pushing its
//   own elems -> h(t+1) cannot complete anywhere before our arm, so no
//   t+2 tx can arrive early. hbuf parity double-buffer: h(t+2) production
//   needs every CTA's h(t+1) push, which follows that CTA's reads of
//   buf[t&1] -> no clobber.
// ---------------------------------------------------------------------------
__global__ __launch_bounds__(256, 1) __cluster_dims__(CL, 1, 1)
void lstm_scan(const float* __restrict__ Whh, float* __restrict__ out) {
    __shared__ __align__(16) float hbuf[2][H_DIM];
    __shared__ __align__(8) unsigned long long bar2[2];

    const uint32_t smem_h = smem_u32(&hbuf[0][0]);
    const uint32_t smem_b = smem_u32(&bar2[0]);

    const int tid = threadIdx.x;
    const int w = tid >> 5;
    const int l = tid & 31;
    const int eidx = l & 3;
    const int s = l >> 2;
    uint32_t rank;
    asm("mov.u32 %0, %%cluster_ctarank;" : "=r"(rank));

    const int E = (int)rank * 32 + 4 * w + eidx;   // global h element

    // weights: 4 gate rows of element E, K slice [32s, 32s+32), packed f32x2.
    unsigned long long wt[4][16];
#pragma unroll
    for (int g = 0; g < 4; g++) {
        const unsigned long long* wr =
            (const unsigned long long*)(Whh + (size_t)(g * H_DIM + E) * H_DIM + 32 * s);
#pragma unroll
        for (int i = 0; i < 16; i++) wt[g][i] = wr[i];
    }

    // init
    for (int i = tid; i < 2 * H_DIM; i += 256) ((float*)hbuf)[i] = 0.0f;
    if (tid < 2) {
        asm volatile("mbarrier.init.shared.b64 [%0], %1;"
                     :: "r"(smem_b + (uint32_t)tid * 8), "r"(1) : "memory");
    }
    __syncthreads();
    if (tid == 0) {
        // pre-arm bar1 for t=1 (h(1) arrives during step 0)
        asm volatile("mbarrier.arrive.expect_tx.shared.b64 _, [%0], %1;"
                     :: "r"(smem_b + 8), "r"(H_DIM * 4) : "memory");
    }
    __syncthreads();
    asm volatile("barrier.cluster.arrive.aligned;" ::: "memory");
    asm volatile("barrier.cluster.wait.aligned;" ::: "memory");

    // push lanes (0-15): lane sends packet p = l>>3 (elems 4w+2p, 4w+2p+1)
    // to dest CTA (l&7): remote hbuf slot + remote bar pair.
    uint32_t dsth = 0, dstb = 0;
    if (l < 16) {
        uint32_t hoff = smem_h + (uint32_t)(rank * 32 + 4 * w + 2 * (l >> 3)) * 4;
#pragma unroll 1
        for (int dummy = 0; dummy < 1; dummy++) {
            asm("mapa.shared::cluster.u32 %0, %1, %2;"
                : "=r"(dsth) : "r"(hoff), "r"(l & 7));
            asm("mapa.shared::cluster.u32 %0, %1, %2;"
                : "=r"(dstb) : "r"(smem_b), "r"(l & 7));
        }
    }

    float c = 0.0f;
    float xn0 = 0.f, xn1 = 0.f, xn2 = 0.f, xn3 = 0.f;
    if (l < 4) {
        xn0 = g_xg[0 * H_DIM + E];
        xn1 = g_xg[1 * H_DIM + E];
        xn2 = g_xg[2 * H_DIM + E];
        xn3 = g_xg[3 * H_DIM + E];
    }

    for (int t = 0; t < T_STEPS; t++) {
        const uint32_t mybar = smem_b + (uint32_t)(t & 1) * 8;
        if (t > 0) mbar_wait(mybar, (uint32_t)(((t - 1) >> 1) & 1));
        if (tid == 0) {
            // re-arm this barrier for step t+2 (before pushing own elems)
            asm volatile("mbarrier.arrive.expect_tx.shared.b64 _, [%0], %1;"
                         :: "r"(mybar), "r"(H_DIM * 4) : "memory");
        }

        // ---- full dots: slice [32s,32s+32) of h ----
        const ulonglong2* hp =
            (const ulonglong2*)((const char*)hbuf + (t & 1) * (H_DIM * 4) + s * 128);
        unsigned long long hh[16];
#pragma unroll
        for (int i = 0; i < 8; i++) {
            ulonglong2 q = hp[i];
            hh[2 * i + 0] = q.x;
            hh[2 * i + 1] = q.y;
        }
        unsigned long long a0 = 0ull, a1 = 0ull, a2 = 0ull, a3 = 0ull;
#pragma unroll
        for (int j = 0; j < 16; j++) {
            ffma2(a0, wt[0][j], hh[j]);
            ffma2(a1, wt[1][j], hh[j]);
            ffma2(a2, wt[2][j], hh[j]);
            ffma2(a3, wt[3][j], hh[j]);
        }
        float si = lo32(a0) + hi32(a0);
        float sf = lo32(a1) + hi32(a1);
        float sg = lo32(a2) + hi32(a2);
        float so = lo32(a3) + hi32(a3);

        // reduce across 8 K-slices (lane bits 2,3,4)
#pragma unroll
        for (int off = 4; off <= 16; off <<= 1) {
            si += __shfl_xor_sync(0xFFFFFFFFu, si, off);
            sf += __shfl_xor_sync(0xFFFFFFFFu, sf, off);
            sg += __shfl_xor_sync(0xFFFFFFFFu, sg, off);
            so += __shfl_xor_sync(0xFFFFFFFFu, so, off);
        }

        // ---- activations (lanes 0-3; c in-lane), MUFU tanh.approx ----
        float hv = 0.0f;
        if (l < 4) {
            float iv = sigmoid_fast(si + xn0);
            float fv = sigmoid_fast(sf + xn1);
            float gv = tanh_fast(sg + xn2);
            float ov = sigmoid_fast(so + xn3);
            c = fv * c + iv * gv;
            hv = ov * tanh_fast(c);
        }

        // ---- pack pairs + push (lanes 0-15: packet l>>3, dest l&7) ----
        if (t < T_STEPS - 1) {
            int srcl = 2 * (l >> 3);   // 0 or 2
            float vlo = __shfl_sync(0xFFFFFFFFu, hv, srcl);
            float vhi = __shfl_sync(0xFFFFFFFFu, hv, srcl + 1);
            if (l < 16) {
                unsigned long long pkt;
                asm("mov.b64 %0, {%1, %2};"
                    : "=l"(pkt) : "r"(__float_as_uint(vlo)),
                                  "r"(__float_as_uint(vhi)));
                const uint32_t hoff = (uint32_t)((t + 1) & 1) * (H_DIM * 4);
                const uint32_t boff = (uint32_t)((t + 1) & 1) * 8;
                asm volatile(
                    "st.async.shared::cluster.mbarrier::complete_tx::bytes.b64 "
                    "[%0], %1, [%2];"
                    :: "r"(dsth + hoff), "l"(pkt), "r"(dstb + boff)
                    : "memory");
            }
        }

        // ---- off critical path: output + next xg prefetch ----
        if (l < 4) {
            out[(size_t)t * H_DIM + E] = hv;
            if (t == T_STEPS - 1) {
                out[(size_t)T_STEPS * H_DIM + E] = hv;
                out[(size_t)T_STEPS * H_DIM + H_DIM + E] = c;
            }
            int tn = (t + 1 < T_STEPS) ? (t + 1) : t;
            const float* xr = g_xg + (size_t)tn * G_DIM + E;
            xn0 = xr[0]; xn1 = xr[256]; xn2 = xr[512]; xn3 = xr[768];
        }
    }
}

// ---------------------------------------------------------------------------
extern "C" void kernel_launch(void* const* d_in, const int* in_sizes, int n_in,
                              void* d_out, int out_size) {
    const int* tokens = (const int*)d_in[0];
    const float* emb = (const float*)d_in[1];
    const float* Wih = (const float*)d_in[2];
    const float* Whh = (const float*)d_in[3];
    const float* bih = (const float*)d_in[4];
    const float* bhh = (const float*)d_in[5];
    float* out = (float*)d_out;

    dim3 gA(8, 64);
    xg_gemm<<<gA, 256>>>(tokens, emb, Wih, bih, bhh);
    lstm_scan<<<CL, 256>>>(Whh, out);
}